// round 2
// baseline (speedup 1.0000x reference)
#include <cuda_runtime.h>
#include <cuda_bf16.h>
#include <cstdint>
#include <math.h>

// Problem dims
#define BB 256
#define TT 128
#define HH 1024
#define OO 47
#define PP 4
#define LL 3
#define GH 4096   // 4*H
#define KK 2048   // H (x part) + H (h part)

// GEMM tile config
#define BM 64
#define BN 128
#define BK 32
#define NKT (KK / BK)          // 64 k-tiles
#define SMEM_BYTES 61440

// ---------------- persistent device state (no allocation allowed) ----------------
// Weights, split hi/lo bf16, rows interleaved: row j' = 4*u + gate, gate order i,f,g,o.
// cols: k<1024 -> W_ih[., k]; k>=1024 -> W_hh[., k-1024]
__device__ __nv_bfloat16 g_Whi[LL][GH][KK];
__device__ __nv_bfloat16 g_Wlo[LL][GH][KK];
__device__ float g_bias[LL][BB][GH];     // b_ih + b_hh (+ properties @ W_ih0[:,1024:] for layer 0), interleaved cols
__device__ float g_c[LL][BB][HH];
__device__ float g_hf[LL][BB][HH];
__device__ __nv_bfloat16 g_hhi[2][LL][BB][HH];  // ping-pong h, hi part
__device__ __nv_bfloat16 g_hlo[2][LL][BB][HH];  // ping-pong h, lo part
__device__ __nv_bfloat16 g_xhi[BB][HH];         // current embedded token input
__device__ __nv_bfloat16 g_xlo[BB][HH];

__device__ __forceinline__ void split2(float v, __nv_bfloat16* hi, __nv_bfloat16* lo) {
    __nv_bfloat16 h = __float2bfloat16(v);
    *hi = h;
    *lo = __float2bfloat16(v - __bfloat162float(h));
}

// ---------------- setup kernels ----------------
__global__ void prep_weights(const float* __restrict__ Wih0,
                             const float* __restrict__ Wihr,
                             const float* __restrict__ Whh) {
    const int total = LL * GH * KK;  // 25.2M
    for (int idx = blockIdx.x * 256 + threadIdx.x; idx < total; idx += gridDim.x * 256) {
        int k  = idx % KK;
        int jp = (idx / KK) % GH;
        int l  = idx / (KK * GH);
        int orig = (jp & 3) * HH + (jp >> 2);   // gate*1024 + unit
        float v;
        if (k < HH) {
            v = (l == 0) ? Wih0[(size_t)orig * (HH + PP) + k]
                         : Wihr[((size_t)(l - 1) * GH + orig) * HH + k];
        } else {
            v = Whh[((size_t)l * GH + orig) * HH + (k - HH)];
        }
        split2(v, &g_Whi[l][jp][k], &g_Wlo[l][jp][k]);
    }
}

__global__ void prep_bias(const float* __restrict__ props,
                          const float* __restrict__ bih,
                          const float* __restrict__ bhh,
                          const float* __restrict__ Wih0) {
    const int total = LL * BB * GH;
    for (int idx = blockIdx.x * 256 + threadIdx.x; idx < total; idx += gridDim.x * 256) {
        int jp = idx % GH;
        int b  = (idx / GH) % BB;
        int l  = idx / (GH * BB);
        int orig = (jp & 3) * HH + (jp >> 2);
        float v = bih[l * GH + orig] + bhh[l * GH + orig];
        if (l == 0) {
            #pragma unroll
            for (int p = 0; p < PP; p++)
                v += props[b * PP + p] * Wih0[(size_t)orig * (HH + PP) + HH + p];
        }
        g_bias[l][b][jp] = v;
    }
}

__global__ void init_state(const float* __restrict__ emb) {
    // one thread per (b, k)
    int idx = blockIdx.x * 256 + threadIdx.x;
    if (idx >= BB * HH) return;
    int b = idx / HH, k = idx % HH;
    #pragma unroll
    for (int l = 0; l < LL; l++) {
        g_c[l][b][k] = 0.f;
        g_hhi[0][l][b][k] = __float2bfloat16(0.f);
        g_hlo[0][l][b][k] = __float2bfloat16(0.f);
    }
    split2(emb[k], &g_xhi[b][k], &g_xlo[b][k]);  // token id 0
}

// ---------------- GEMM + LSTM fused kernel ----------------
__device__ __forceinline__ void cp16(uint32_t dst, const void* src) {
    asm volatile("cp.async.cg.shared.global [%0], [%1], 16;\n" :: "r"(dst), "l"(src));
}
__device__ __forceinline__ void ldm_x4(uint32_t addr, uint32_t& r0, uint32_t& r1,
                                       uint32_t& r2, uint32_t& r3) {
    asm volatile("ldmatrix.sync.aligned.m8n8.x4.shared.b16 {%0,%1,%2,%3}, [%4];\n"
                 : "=r"(r0), "=r"(r1), "=r"(r2), "=r"(r3) : "r"(addr));
}
__device__ __forceinline__ void mma16816(float* c, const uint32_t* a, const uint32_t* b) {
    asm volatile("mma.sync.aligned.m16n8k16.row.col.f32.bf16.bf16.f32 "
                 "{%0,%1,%2,%3},{%4,%5,%6,%7},{%8,%9},{%0,%1,%2,%3};\n"
                 : "+f"(c[0]), "+f"(c[1]), "+f"(c[2]), "+f"(c[3])
                 : "r"(a[0]), "r"(a[1]), "r"(a[2]), "r"(a[3]), "r"(b[0]), "r"(b[1]));
}

// smem layout (bf16 units), rows padded to 40 elems (80B) for conflict-free ldmatrix
__device__ __forceinline__ int SA(int st, int pr, int r, int c) {
    return ((st * 2 + pr) * BM + r) * 40 + c;
}
__device__ __forceinline__ int SW(int st, int pr, int r, int c) {
    return 2 * 2 * BM * 40 + ((st * 2 + pr) * BN + r) * 40 + c;
}

__global__ __launch_bounds__(256, 1)
void lstm_layer_kernel(int l, int p) {
    extern __shared__ __nv_bfloat16 smem[];
    const int tid  = threadIdx.x;
    const int ctaN = blockIdx.x;   // 0..31  (gate-col tile, 32 units * 4 gates)
    const int ctaM = blockIdx.y;   // 0..3   (batch tile of 64)
    const int q = p ^ 1;

    const __nv_bfloat16* __restrict__ A0hi = (l == 0) ? &g_xhi[0][0] : &g_hhi[q][l - 1][0][0];
    const __nv_bfloat16* __restrict__ A0lo = (l == 0) ? &g_xlo[0][0] : &g_hlo[q][l - 1][0][0];
    const __nv_bfloat16* __restrict__ A1hi = &g_hhi[p][l][0][0];
    const __nv_bfloat16* __restrict__ A1lo = &g_hlo[p][l][0][0];
    const __nv_bfloat16* __restrict__ Whi  = &g_Whi[l][0][0];
    const __nv_bfloat16* __restrict__ Wlo  = &g_Wlo[l][0][0];

    uint32_t sbase;
    asm("{ .reg .u64 t; cvta.to.shared.u64 t, %1; cvt.u32.u64 %0, t; }"
        : "=r"(sbase) : "l"(smem));

    const int arow = tid >> 2;     // 0..63
    const int ach  = tid & 3;      // 16B chunk within 32-elem row
    const int warp = tid >> 5, lane = tid & 31;
    const int wm = warp >> 2, wn = warp & 3;   // warp grid 2(M) x 4(N); warp tile 32x32

    float acc[2][4][4];
    #pragma unroll
    for (int a = 0; a < 2; a++)
        #pragma unroll
        for (int b = 0; b < 4; b++)
            #pragma unroll
            for (int v = 0; v < 4; v++) acc[a][b][v] = 0.f;

    auto load_tile = [&](int kt, int st) {
        const int kg = kt * BK;
        const int k = kg + ach * 8;
        {   // A tile 64x32 (hi+lo)
            const int m = ctaM * BM + arow;
            const __nv_bfloat16* bh = (k < HH) ? A0hi : A1hi;
            const __nv_bfloat16* bl = (k < HH) ? A0lo : A1lo;
            const int kk = k & (HH - 1);
            cp16(sbase + 2u * SA(st, 0, arow, ach * 8), bh + (size_t)m * HH + kk);
            cp16(sbase + 2u * SA(st, 1, arow, ach * 8), bl + (size_t)m * HH + kk);
        }
        #pragma unroll
        for (int rr = 0; rr < 2; rr++) {  // W tile 128x32 (hi+lo), 2 rows per thread
            const int r = arow + rr * 64;
            const int n = ctaN * BN + r;
            cp16(sbase + 2u * SW(st, 0, r, ach * 8), Whi + (size_t)n * KK + k);
            cp16(sbase + 2u * SW(st, 1, r, ach * 8), Wlo + (size_t)n * KK + k);
        }
    };

    load_tile(0, 0);
    asm volatile("cp.async.commit_group;\n");

    for (int kt = 0; kt < NKT; kt++) {
        const int st = kt & 1;
        if (kt + 1 < NKT) {
            load_tile(kt + 1, st ^ 1);
            asm volatile("cp.async.commit_group;\n");
            asm volatile("cp.async.wait_group 1;\n");
        } else {
            asm volatile("cp.async.wait_group 0;\n");
        }
        __syncthreads();

        #pragma unroll
        for (int kf = 0; kf < 2; kf++) {
            uint32_t ahi[2][4], alo[2][4];
            #pragma unroll
            for (int mf = 0; mf < 2; mf++) {
                const int r = wm * 32 + mf * 16 + (lane & 15);
                const int c = kf * 16 + ((lane >> 4) & 1) * 8;
                ldm_x4(sbase + 2u * SA(st, 0, r, c), ahi[mf][0], ahi[mf][1], ahi[mf][2], ahi[mf][3]);
                ldm_x4(sbase + 2u * SA(st, 1, r, c), alo[mf][0], alo[mf][1], alo[mf][2], alo[mf][3]);
            }
            uint32_t bhi[4][2], blo[4][2];
            #pragma unroll
            for (int g2 = 0; g2 < 2; g2++) {
                const int r = wn * 32 + g2 * 16 + (lane & 7) + ((lane >> 4) & 1) * 8;
                const int c = kf * 16 + ((lane >> 3) & 1) * 8;
                uint32_t r0, r1, r2, r3;
                ldm_x4(sbase + 2u * SW(st, 0, r, c), r0, r1, r2, r3);
                bhi[g2 * 2][0] = r0; bhi[g2 * 2][1] = r1;
                bhi[g2 * 2 + 1][0] = r2; bhi[g2 * 2 + 1][1] = r3;
                ldm_x4(sbase + 2u * SW(st, 1, r, c), r0, r1, r2, r3);
                blo[g2 * 2][0] = r0; blo[g2 * 2][1] = r1;
                blo[g2 * 2 + 1][0] = r2; blo[g2 * 2 + 1][1] = r3;
            }
            #pragma unroll
            for (int mf = 0; mf < 2; mf++)
                #pragma unroll
                for (int nf = 0; nf < 4; nf++) {
                    mma16816(acc[mf][nf], ahi[mf], bhi[nf]);  // hi*hi
                    mma16816(acc[mf][nf], ahi[mf], blo[nf]);  // hi*lo
                    mma16816(acc[mf][nf], alo[mf], bhi[nf]);  // lo*hi
                }
        }
        __syncthreads();
    }

    // epilogue: stage gates in smem (reuse pipeline buffers), then fused LSTM update
    float* gs = reinterpret_cast<float*>(smem);   // [BM][BN]
    #pragma unroll
    for (int mf = 0; mf < 2; mf++)
        #pragma unroll
        for (int nf = 0; nf < 4; nf++) {
            const int r = wm * 32 + mf * 16 + (lane >> 2);
            const int c = wn * 32 + nf * 8 + (lane & 3) * 2;
            gs[r * BN + c]           = acc[mf][nf][0];
            gs[r * BN + c + 1]       = acc[mf][nf][1];
            gs[(r + 8) * BN + c]     = acc[mf][nf][2];
            gs[(r + 8) * BN + c + 1] = acc[mf][nf][3];
        }
    __syncthreads();

    for (int it = tid; it < BM * 32; it += 256) {
        const int row = it >> 5, u = it & 31;
        const int b  = ctaM * BM + row;
        const int hu = ctaN * 32 + u;
        const float* bptr = &g_bias[l][b][ctaN * BN + u * 4];
        const float gi = gs[row * BN + u * 4 + 0] + bptr[0];
        const float gf = gs[row * BN + u * 4 + 1] + bptr[1];
        const float gg = gs[row * BN + u * 4 + 2] + bptr[2];
        const float go = gs[row * BN + u * 4 + 3] + bptr[3];
        const float si = 1.f / (1.f + expf(-gi));
        const float sf = 1.f / (1.f + expf(-gf));
        const float so = 1.f / (1.f + expf(-go));
        const float cn = sf * g_c[l][b][hu] + si * tanhf(gg);
        const float hn = so * tanhf(cn);
        g_c[l][b][hu]  = cn;
        g_hf[l][b][hu] = hn;
        split2(hn, &g_hhi[q][l][b][hu], &g_hlo[q][l][b][hu]);
    }
}

// ---------------- decode: logits + argmax + embed next token ----------------
__global__ __launch_bounds__(128)
void decode_kernel(const float* __restrict__ Wdec, const float* __restrict__ bdec,
                   const float* __restrict__ emb, float* __restrict__ out, int t) {
    __shared__ float4 sh4[HH / 4];
    __shared__ float sl[OO];
    __shared__ int snxt;
    const int b = blockIdx.x, tid = threadIdx.x;
    const float4* __restrict__ h4 = reinterpret_cast<const float4*>(&g_hf[LL - 1][b][0]);
    for (int k = tid; k < HH / 4; k += 128) sh4[k] = h4[k];
    __syncthreads();
    const int w = tid >> 5, lane = tid & 31;
    for (int o = w; o < OO; o += 4) {
        const float4* wr = reinterpret_cast<const float4*>(Wdec + (size_t)o * HH);
        float s = 0.f;
        for (int k = lane; k < HH / 4; k += 32) {
            float4 a = sh4[k], c = wr[k];
            s += a.x * c.x + a.y * c.y + a.z * c.z + a.w * c.w;
        }
        #pragma unroll
        for (int off = 16; off; off >>= 1) s += __shfl_xor_sync(0xffffffffu, s, off);
        if (lane == 0) sl[o] = s + bdec[o];
    }
    __syncthreads();
    if (tid < OO) out[((size_t)b * TT + t) * OO + tid] = sl[tid];
    if (tid == 0) {
        float best = sl[0]; int bi = 0;
        #pragma unroll
        for (int o = 1; o < OO; o++)
            if (sl[o] > best) { best = sl[o]; bi = o; }
        snxt = bi;
    }
    __syncthreads();
    const float* er = emb + (size_t)snxt * HH;
    for (int k = tid; k < HH; k += 128) split2(er[k], &g_xhi[b][k], &g_xlo[b][k]);
}

// ---------------- final h/c copy into output ----------------
__global__ void final_copy(float* __restrict__ out) {
    const int LBH = LL * BB * HH;
    float* dst = out + (size_t)BB * TT * OO;
    const float* hsrc = &g_hf[0][0][0];
    const float* csrc = &g_c[0][0][0];
    for (int idx = blockIdx.x * 256 + threadIdx.x; idx < 2 * LBH; idx += gridDim.x * 256) {
        dst[idx] = (idx < LBH) ? hsrc[idx] : csrc[idx - LBH];
    }
}

// ---------------- host launcher ----------------
extern "C" void kernel_launch(void* const* d_in, const int* in_sizes, int n_in,
                              void* d_out, int out_size) {
    // metadata order: x, properties, emb, W_dec, b_dec, W_ih0, W_ih_rest, W_hh, b_ih, b_hh
    const float* props = (const float*)d_in[1];
    const float* emb   = (const float*)d_in[2];
    const float* Wdec  = (const float*)d_in[3];
    const float* bdec  = (const float*)d_in[4];
    const float* Wih0  = (const float*)d_in[5];
    const float* Wihr  = (const float*)d_in[6];
    const float* Whh   = (const float*)d_in[7];
    const float* bih   = (const float*)d_in[8];
    const float* bhh   = (const float*)d_in[9];
    float* out = (float*)d_out;

    cudaFuncSetAttribute(lstm_layer_kernel,
                         cudaFuncAttributeMaxDynamicSharedMemorySize, SMEM_BYTES);

    prep_weights<<<8192, 256>>>(Wih0, Wihr, Whh);
    prep_bias<<<4096, 256>>>(props, bih, bhh, Wih0);
    init_state<<<(BB * HH + 255) / 256, 256>>>(emb);

    dim3 grid(GH / BN, BB / BM);  // (32, 4) = 128 CTAs
    for (int t = 0; t < TT; t++) {
        const int p = t & 1;
        for (int l = 0; l < LL; l++)
            lstm_layer_kernel<<<grid, 256, SMEM_BYTES>>>(l, p);
        decode_kernel<<<BB, 128>>>(Wdec, bdec, emb, out, t);
    }
    final_copy<<<4096, 256>>>(out);
}